// round 1
// baseline (speedup 1.0000x reference)
#include <cuda_runtime.h>

// Custom_RoPE: x (32, 8192, 128) fp32, cos/sin (8192, 128) fp32.
// out = x*cos + rotate_half(x)*sin ; obs_max/min over last dim.
// d_out layout (flattened tuple): out[H*T*D] | obs_max[H*T] | obs_min[H*T].
// scale_x / scale_cos / scale_sin inputs are unused by the reference.

#define RH 32
#define RT 8192
#define RD 128
#define HALF 64

__global__ __launch_bounds__(256) void rope_kernel(
    const float* __restrict__ x,
    const float* __restrict__ cosp,
    const float* __restrict__ sinp,
    float* __restrict__ out,
    float* __restrict__ omax,
    float* __restrict__ omin)
{
    const unsigned FULL = 0xffffffffu;
    int row  = (blockIdx.x * blockDim.x + threadIdx.x) >> 5;   // [0, H*T)
    int lane = threadIdx.x & 31;

    int t = row & (RT - 1);
    size_t xbase = (size_t)row * RD;
    size_t cbase = (size_t)t   * RD;

    // lane l covers elements [4l, 4l+3]; lanes 0-15 = first half, 16-31 = second half
    float4 xv = reinterpret_cast<const float4*>(x    + xbase)[lane];
    float4 cv = reinterpret_cast<const float4*>(cosp + cbase)[lane];
    float4 sv = reinterpret_cast<const float4*>(sinp + cbase)[lane];

    // partner half via xor-16 shuffle: element e pairs with e^64
    float4 px;
    px.x = __shfl_xor_sync(FULL, xv.x, 16);
    px.y = __shfl_xor_sync(FULL, xv.y, 16);
    px.z = __shfl_xor_sync(FULL, xv.z, 16);
    px.w = __shfl_xor_sync(FULL, xv.w, 16);

    // first half: x1*c - x2*s ; second half: x2*c + x1*s
    float sgn = (lane < 16) ? -1.0f : 1.0f;

    float4 o;
    o.x = fmaf(sgn * px.x, sv.x, xv.x * cv.x);
    o.y = fmaf(sgn * px.y, sv.y, xv.y * cv.y);
    o.z = fmaf(sgn * px.z, sv.z, xv.z * cv.z);
    o.w = fmaf(sgn * px.w, sv.w, xv.w * cv.w);

    reinterpret_cast<float4*>(out + xbase)[lane] = o;

    // per-row max/min reduction
    float mx = fmaxf(fmaxf(o.x, o.y), fmaxf(o.z, o.w));
    float mn = fminf(fminf(o.x, o.y), fminf(o.z, o.w));
    #pragma unroll
    for (int off = 16; off > 0; off >>= 1) {
        mx = fmaxf(mx, __shfl_xor_sync(FULL, mx, off));
        mn = fminf(mn, __shfl_xor_sync(FULL, mn, off));
    }
    if (lane == 0) {
        omax[row] = mx;
        omin[row] = mn;
    }
}

extern "C" void kernel_launch(void* const* d_in, const int* in_sizes, int n_in,
                              void* d_out, int out_size)
{
    // inputs: 0=x, 1=scale_x (unused), 2=cos, 3=scale_cos (unused),
    //         4=sin, 5=scale_sin (unused)
    const float* x    = (const float*)d_in[0];
    const float* cosp = (const float*)d_in[2];
    const float* sinp = (const float*)d_in[4];

    float* out  = (float*)d_out;
    float* omax = out + (size_t)RH * RT * RD;
    float* omin = omax + (size_t)RH * RT;

    const int rows = RH * RT;              // 262144
    const int warps_per_block = 8;         // 256 threads
    const int blocks = rows / warps_per_block;

    rope_kernel<<<blocks, warps_per_block * 32>>>(x, cosp, sinp, out, omax, omin);
}

// round 2
// speedup vs baseline: 1.1773x; 1.1773x over previous
#include <cuda_runtime.h>

// Custom_RoPE: x (32, 8192, 128) fp32, cos/sin (8192, 128) fp32.
// out = x*cos + rotate_half(x)*sin ; obs_max/min over last dim.
// d_out layout: out[H*T*D] | obs_max[H*T] | obs_min[H*T].
// scale_x / scale_cos / scale_sin are unused by the reference.
//
// R1: one warp = two rows sharing the same t (heads h and h+16).
//  - lanes 0-15 handle row0, lanes 16-31 handle row1
//  - each lane loads BOTH halves (lo at 4*ll, hi at 64+4*ll) -> rotate needs
//    zero shuffles
//  - cos/sin loaded once per warp (identical addresses across half-warps,
//    HW dedups the sectors)
//  - max/min butterfly over 16 lanes (offsets 8,4,2,1) reduces both rows
//    at once in disjoint half-warps
//  - __ldcs on x, __stcs on out: streaming hints keep cos/sin L2-resident

#define RH 32
#define RT 8192
#define RD 128

__global__ __launch_bounds__(256) void rope_kernel(
    const float* __restrict__ x,
    const float* __restrict__ cosp,
    const float* __restrict__ sinp,
    float* __restrict__ out,
    float* __restrict__ omax,
    float* __restrict__ omin)
{
    const unsigned FULL = 0xffffffffu;
    int w    = (blockIdx.x * blockDim.x + threadIdx.x) >> 5;  // [0, H/2 * T)
    int lane = threadIdx.x & 31;
    int ll   = lane & 15;          // lane within half-warp
    int half = lane >> 4;          // 0 -> row0 (head h), 1 -> row1 (head h+16)

    int t = w & (RT - 1);
    int h = w >> 13;               // [0, 16)

    size_t row = (size_t)(h + half * 16) * RT + t;
    size_t xb  = row * RD;
    size_t cb  = (size_t)t * RD;

    const float4* xlo_p = reinterpret_cast<const float4*>(x + xb)      + ll;
    const float4* xhi_p = reinterpret_cast<const float4*>(x + xb + 64) + ll;
    const float4* clo_p = reinterpret_cast<const float4*>(cosp + cb)      + ll;
    const float4* chi_p = reinterpret_cast<const float4*>(cosp + cb + 64) + ll;
    const float4* slo_p = reinterpret_cast<const float4*>(sinp + cb)      + ll;
    const float4* shi_p = reinterpret_cast<const float4*>(sinp + cb + 64) + ll;

    // front-batched loads: 6 independent LDG.128 in flight
    float4 xlo = __ldcs(xlo_p);
    float4 xhi = __ldcs(xhi_p);
    float4 clo = *clo_p;
    float4 chi = *chi_p;
    float4 slo = *slo_p;
    float4 shi = *shi_p;

    // first half:  x1*c - x2*s ; second half: x2*c + x1*s
    float4 olo, ohi;
    olo.x = fmaf(-xhi.x, slo.x, xlo.x * clo.x);
    olo.y = fmaf(-xhi.y, slo.y, xlo.y * clo.y);
    olo.z = fmaf(-xhi.z, slo.z, xlo.z * clo.z);
    olo.w = fmaf(-xhi.w, slo.w, xlo.w * clo.w);
    ohi.x = fmaf( xlo.x, shi.x, xhi.x * chi.x);
    ohi.y = fmaf( xlo.y, shi.y, xhi.y * chi.y);
    ohi.z = fmaf( xlo.z, shi.z, xhi.z * chi.z);
    ohi.w = fmaf( xlo.w, shi.w, xhi.w * chi.w);

    __stcs(reinterpret_cast<float4*>(out + xb)      + ll, olo);
    __stcs(reinterpret_cast<float4*>(out + xb + 64) + ll, ohi);

    // per-row max/min: butterfly over 16-lane halves (offsets stay in-half)
    float mx = fmaxf(fmaxf(fmaxf(olo.x, olo.y), fmaxf(olo.z, olo.w)),
                     fmaxf(fmaxf(ohi.x, ohi.y), fmaxf(ohi.z, ohi.w)));
    float mn = fminf(fminf(fminf(olo.x, olo.y), fminf(olo.z, olo.w)),
                     fminf(fminf(ohi.x, ohi.y), fminf(ohi.z, ohi.w)));
    #pragma unroll
    for (int off = 8; off > 0; off >>= 1) {
        mx = fmaxf(mx, __shfl_xor_sync(FULL, mx, off));
        mn = fminf(mn, __shfl_xor_sync(FULL, mn, off));
    }
    if (ll == 0) {
        omax[row] = mx;
        omin[row] = mn;
    }
}

extern "C" void kernel_launch(void* const* d_in, const int* in_sizes, int n_in,
                              void* d_out, int out_size)
{
    // inputs: 0=x, 1=scale_x (unused), 2=cos, 3=scale_cos (unused),
    //         4=sin, 5=scale_sin (unused)
    const float* x    = (const float*)d_in[0];
    const float* cosp = (const float*)d_in[2];
    const float* sinp = (const float*)d_in[4];

    float* out  = (float*)d_out;
    float* omax = out + (size_t)RH * RT * RD;
    float* omin = omax + (size_t)RH * RT;

    const int warps = (RH / 2) * RT;        // 131072 (2 rows per warp)
    const int warps_per_block = 8;          // 256 threads
    const int blocks = warps / warps_per_block;

    rope_kernel<<<blocks, warps_per_block * 32>>>(x, cosp, sinp, out, omax, omin);
}